// round 1
// baseline (speedup 1.0000x reference)
#include <cuda_runtime.h>
#include <math.h>

#define BNUM  50
#define E0    600000
#define FIN   256
#define NH    128
#define N0MAX 100000
#define N1MAX 80000

// ---------------- scratch (device globals; no allocs allowed) ----------------
__device__ float g_h[N0MAX * NH];        // GEMM output h = x @ W
__device__ float g_xa[N0MAX * NH];       // conv output x' (post-relu)
__device__ float g_xb[N1MAX * NH];       // pooled features
__device__ float g_hs[N0MAX];            // score projection h_s = x' @ Ws
__device__ float g_score[N0MAX];
__device__ int   g_deg[N0MAX];
__device__ float g_dis[N0MAX];           // rsqrt(deg+1)
__device__ float g_dinv[N0MAX];          // 1/(deg+1)
__device__ int   g_rowptr[N0MAX + 1];
__device__ int   g_cursor[N0MAX];
__device__ int   g_exsc[N0MAX];
__device__ int   g_bsum[128];
__device__ int   g_csr[E0];              // src ids bucketed by dst
__device__ int   g_esrc0[E0], g_edst0[E0];
__device__ int   g_esrc1[E0], g_edst1[E0];
__device__ int   g_perm[N1MAX];
__device__ int   g_map[N0MAX];
__device__ float g_x123[BNUM * 2 * NH];  // x1+x2+x3 accumulator
__device__ int   g_cnt[4];               // [0]=E stage1, [1]=E after pool1, [2]=after pool2

// ---------------- kernels ----------------
__global__ void k_init() {
    int t = blockIdx.x * blockDim.x + threadIdx.x;
    if (t < BNUM * 2 * NH) g_x123[t] = 0.f;
    if (t == 0) { g_cnt[0] = E0; g_cnt[1] = 0; g_cnt[2] = 0; }
}

__global__ void k_reset(int N) {
    int i = blockIdx.x * blockDim.x + threadIdx.x;
    if (i < N) { g_deg[i] = 0; g_map[i] = -1; }
}

__global__ void k_count(const int* __restrict__ dst, const int* __restrict__ cnt) {
    int i = blockIdx.x * blockDim.x + threadIdx.x;
    if (i < *cnt) atomicAdd(&g_deg[dst[i]], 1);
}

__global__ void k_degnorm(int N) {
    int i = blockIdx.x * blockDim.x + threadIdx.x;
    if (i < N) {
        float d = (float)g_deg[i] + 1.0f;
        g_dinv[i] = 1.0f / d;
        g_dis[i]  = rsqrtf(d);
    }
}

__global__ void k_scan1(int N) {
    __shared__ int sm[1024];
    int i = blockIdx.x * 1024 + threadIdx.x;
    int v = (i < N) ? g_deg[i] : 0;
    sm[threadIdx.x] = v;
    __syncthreads();
    for (int off = 1; off < 1024; off <<= 1) {
        int t = (threadIdx.x >= off) ? sm[threadIdx.x - off] : 0;
        __syncthreads();
        sm[threadIdx.x] += t;
        __syncthreads();
    }
    if (i < N) g_exsc[i] = sm[threadIdx.x] - v;
    if (threadIdx.x == 1023) g_bsum[blockIdx.x] = sm[1023];
}

__global__ void k_scan2(int nb) {
    if (threadIdx.x == 0) {
        int run = 0;
        for (int i = 0; i < nb; i++) { int t = g_bsum[i]; g_bsum[i] = run; run += t; }
    }
}

__global__ void k_scan3(int N, const int* __restrict__ cnt) {
    int i = blockIdx.x * blockDim.x + threadIdx.x;
    if (i < N) {
        int r = g_exsc[i] + g_bsum[i >> 10];
        g_rowptr[i] = r;
        g_cursor[i] = r;
    }
    if (i == 0) g_rowptr[N] = *cnt;
}

__global__ void k_csr(const int* __restrict__ src, const int* __restrict__ dst,
                      const int* __restrict__ cnt) {
    int i = blockIdx.x * blockDim.x + threadIdx.x;
    if (i < *cnt) {
        int d = dst[i];
        int p = atomicAdd(&g_cursor[d], 1);
        g_csr[p] = src[i];
    }
}

// h = X @ W   (X: [N,F] row-major, W: [F,128] row-major) -> g_h
// BM=128, BN=128, BK=16, 256 threads, 8x8 register tile per thread
__launch_bounds__(256)
__global__ void k_gemm(const float* __restrict__ X, const float* __restrict__ W,
                       int N, int F) {
    __shared__ float As[16 * 128];   // transposed: As[kk][row]
    __shared__ float Bs[16 * 128];   // Bs[kk][col]
    int tid = threadIdx.x;
    int tx = tid & 15, ty = tid >> 4;
    int rowBase = blockIdx.x * 128;
    float acc[8][8];
    #pragma unroll
    for (int r = 0; r < 8; r++)
        #pragma unroll
        for (int c = 0; c < 8; c++) acc[r][c] = 0.f;

    for (int kt = 0; kt < F; kt += 16) {
        #pragma unroll
        for (int q2 = 0; q2 < 2; q2++) {
            int q = tid * 2 + q2;
            int ar = q >> 2, ac4 = q & 3;
            int grow = rowBase + ar;
            float4 v = make_float4(0.f, 0.f, 0.f, 0.f);
            if (grow < N) v = *(const float4*)&X[(size_t)grow * F + kt + ac4 * 4];
            As[(ac4 * 4 + 0) * 128 + ar] = v.x;
            As[(ac4 * 4 + 1) * 128 + ar] = v.y;
            As[(ac4 * 4 + 2) * 128 + ar] = v.z;
            As[(ac4 * 4 + 3) * 128 + ar] = v.w;
        }
        #pragma unroll
        for (int q2 = 0; q2 < 2; q2++) {
            int q = tid * 2 + q2;
            int br = q >> 5, bc4 = q & 31;
            *(float4*)&Bs[br * 128 + bc4 * 4] =
                *(const float4*)&W[(size_t)(kt + br) * 128 + bc4 * 4];
        }
        __syncthreads();
        #pragma unroll
        for (int kk = 0; kk < 16; kk++) {
            float4 a0 = *(float4*)&As[kk * 128 + ty * 8];
            float4 a1 = *(float4*)&As[kk * 128 + ty * 8 + 4];
            float4 b0 = *(float4*)&Bs[kk * 128 + tx * 8];
            float4 b1 = *(float4*)&Bs[kk * 128 + tx * 8 + 4];
            float a[8] = {a0.x, a0.y, a0.z, a0.w, a1.x, a1.y, a1.z, a1.w};
            float b[8] = {b0.x, b0.y, b0.z, b0.w, b1.x, b1.y, b1.z, b1.w};
            #pragma unroll
            for (int r = 0; r < 8; r++)
                #pragma unroll
                for (int c = 0; c < 8; c++) acc[r][c] += a[r] * b[c];
        }
        __syncthreads();
    }
    #pragma unroll
    for (int r = 0; r < 8; r++) {
        int grow = rowBase + ty * 8 + r;
        if (grow < N) {
            *(float4*)&g_h[(size_t)grow * NH + tx * 8] =
                make_float4(acc[r][0], acc[r][1], acc[r][2], acc[r][3]);
            *(float4*)&g_h[(size_t)grow * NH + tx * 8 + 4] =
                make_float4(acc[r][4], acc[r][5], acc[r][6], acc[r][7]);
        }
    }
}

// warp per node: x' = relu(sum_in h[src]*dis[src]*dis[n] + h[n]/deg + b); also h_s = x' . Ws
__global__ void k_agg(const float* __restrict__ b, const float* __restrict__ Ws, int N) {
    int gid = blockIdx.x * blockDim.x + threadIdx.x;
    int w = gid >> 5, lane = gid & 31;
    if (w >= N) return;
    int beg = g_rowptr[w], end = g_rowptr[w + 1];
    float dn = g_dis[w];
    float4 acc = make_float4(0.f, 0.f, 0.f, 0.f);
    for (int e = beg; e < end; e++) {
        int s = g_csr[e];
        float nm = g_dis[s] * dn;
        float4 hv = *(const float4*)&g_h[s * NH + lane * 4];
        acc.x += hv.x * nm; acc.y += hv.y * nm;
        acc.z += hv.z * nm; acc.w += hv.w * nm;
    }
    float di = g_dinv[w];
    float4 hw = *(const float4*)&g_h[w * NH + lane * 4];
    float4 bb = *(const float4*)&b[lane * 4];
    float4 o;
    o.x = fmaxf(acc.x + hw.x * di + bb.x, 0.f);
    o.y = fmaxf(acc.y + hw.y * di + bb.y, 0.f);
    o.z = fmaxf(acc.z + hw.z * di + bb.z, 0.f);
    o.w = fmaxf(acc.w + hw.w * di + bb.w, 0.f);
    *(float4*)&g_xa[w * NH + lane * 4] = o;
    float4 wv = *(const float4*)&Ws[lane * 4];
    float d = o.x * wv.x + o.y * wv.y + o.z * wv.z + o.w * wv.w;
    #pragma unroll
    for (int off = 16; off; off >>= 1) d += __shfl_xor_sync(0xffffffffu, d, off);
    if (lane == 0) g_hs[w] = d;
}

// thread per node: score = sum_in hs[src]*dis[src]*dis[n] + hs[n]/deg + bs
__global__ void k_sagg(const float* __restrict__ bs, int N) {
    int i = blockIdx.x * blockDim.x + threadIdx.x;
    if (i >= N) return;
    int beg = g_rowptr[i], end = g_rowptr[i + 1];
    float s = 0.f;
    for (int e = beg; e < end; e++) {
        int u = g_csr[e];
        s += g_hs[u] * g_dis[u];
    }
    g_score[i] = s * g_dis[i] + g_hs[i] * g_dinv[i] + bs[0];
}

// block per graph: full bitonic sort of (score desc, idx asc) over <=2048, emit top-k
__launch_bounds__(1024)
__global__ void k_topk(int n, int k) {
    __shared__ float ss[2048];
    __shared__ int   si[2048];
    int g = blockIdx.x, tid = threadIdx.x;
    for (int j = tid; j < 2048; j += 1024) {
        ss[j] = (j < n) ? g_score[g * n + j] : -3.402823466e38f;
        si[j] = j;
    }
    __syncthreads();
    for (int kk = 2; kk <= 2048; kk <<= 1) {
        for (int jj = kk >> 1; jj > 0; jj >>= 1) {
            for (int i = tid; i < 2048; i += 1024) {
                int l = i ^ jj;
                if (l > i) {
                    float si_ = ss[i], sl_ = ss[l];
                    int ii_ = si[i], il_ = si[l];
                    bool before = (si_ > sl_) || (si_ == sl_ && ii_ < il_);
                    bool asc = ((i & kk) == 0);
                    if (asc != before) {
                        ss[i] = sl_; ss[l] = si_;
                        si[i] = il_; si[l] = ii_;
                    }
                }
            }
            __syncthreads();
        }
    }
    for (int j = tid; j < k; j += 1024) {
        int p = g * n + si[j];
        g_perm[g * k + j] = p;
        g_map[p] = g * k + j;
    }
}

__global__ void k_pool(int Nnew) {
    int t = blockIdx.x * blockDim.x + threadIdx.x;
    int node = t >> 5, lane = t & 31;
    if (node >= Nnew) return;
    int p = g_perm[node];
    float ts = tanhf(g_score[p]);
    float4 v = *(const float4*)&g_xa[p * NH + lane * 4];
    v.x *= ts; v.y *= ts; v.z *= ts; v.w *= ts;
    *(float4*)&g_xb[node * NH + lane * 4] = v;
}

__global__ void k_filter(const int* __restrict__ src, const int* __restrict__ dst,
                         const int* __restrict__ cnt,
                         int* __restrict__ nsrc, int* __restrict__ ndst,
                         int* __restrict__ ncnt) {
    int i = blockIdx.x * blockDim.x + threadIdx.x;
    if (i >= *cnt) return;
    int a = g_map[src[i]], b = g_map[dst[i]];
    if (a >= 0 && b >= 0) {
        int p = atomicAdd(ncnt, 1);
        nsrc[p] = a; ndst[p] = b;
    }
}

__global__ void k_readout(int k) {
    int g = blockIdx.x, f = threadIdx.x;
    const float* base = &g_xb[(size_t)g * k * NH + f];
    float mx = -3.402823466e38f, sm = 0.f;
    for (int i = 0; i < k; i++) {
        float v = base[(size_t)i * NH];
        mx = fmaxf(mx, v);
        sm += v;
    }
    g_x123[g * (2 * NH) + f]      += mx;
    g_x123[g * (2 * NH) + NH + f] += sm / (float)k;
}

__global__ void k_final(const float* __restrict__ Wl, const float* __restrict__ bl,
                        float* __restrict__ out) {
    int g = blockIdx.x, o = threadIdx.x;
    float acc = bl[o];
    #pragma unroll 4
    for (int f = 0; f < 2 * NH; f++)
        acc = fmaf(g_x123[g * (2 * NH) + f], Wl[f * NH + o], acc);
    out[g * NH + o] = fmaxf(acc, 0.f);
}

// ---------------- host driver ----------------
static void run_stage(const float* xin, int F, int Nin, int n, int k,
                      const float* W, const float* b, const float* Ws, const float* bs,
                      const int* src, const int* dst, const int* cnt,
                      int* nsrc, int* ndst, int* ncnt, bool filter) {
    const int EB = (E0 + 255) / 256;
    int nb = (Nin + 1023) / 1024;
    k_reset<<<(Nin + 255) / 256, 256>>>(Nin);
    k_count<<<EB, 256>>>(dst, cnt);
    k_degnorm<<<(Nin + 255) / 256, 256>>>(Nin);
    k_scan1<<<nb, 1024>>>(Nin);
    k_scan2<<<1, 32>>>(nb);
    k_scan3<<<(Nin + 255) / 256, 256>>>(Nin, cnt);
    k_csr<<<EB, 256>>>(src, dst, cnt);
    k_gemm<<<(Nin + 127) / 128, 256>>>(xin, W, Nin, F);
    k_agg<<<(Nin * 32 + 255) / 256, 256>>>(b, Ws, Nin);
    k_sagg<<<(Nin + 255) / 256, 256>>>(bs, Nin);
    k_topk<<<BNUM, 1024>>>(n, k);
    int Nnew = BNUM * k;
    k_pool<<<(Nnew * 32 + 255) / 256, 256>>>(Nnew);
    k_readout<<<BNUM, NH>>>(k);
    if (filter) k_filter<<<EB, 256>>>(src, dst, cnt, nsrc, ndst, ncnt);
}

extern "C" void kernel_launch(void* const* d_in, const int* in_sizes, int n_in,
                              void* d_out, int out_size) {
    const float* x   = (const float*)d_in[0];
    const float* W1  = (const float*)d_in[1];
    const float* b1  = (const float*)d_in[2];
    const float* Ws1 = (const float*)d_in[3];
    const float* bs1 = (const float*)d_in[4];
    const float* W2  = (const float*)d_in[5];
    const float* b2  = (const float*)d_in[6];
    const float* Ws2 = (const float*)d_in[7];
    const float* bs2 = (const float*)d_in[8];
    const float* W3  = (const float*)d_in[9];
    const float* b3  = (const float*)d_in[10];
    const float* Ws3 = (const float*)d_in[11];
    const float* bs3 = (const float*)d_in[12];
    const float* Wl  = (const float*)d_in[13];
    const float* bl  = (const float*)d_in[14];
    const int*   ei  = (const int*)d_in[15];
    float* out = (float*)d_out;

    int *p_es0, *p_ed0, *p_es1, *p_ed1, *p_cnt;
    float* p_xb;
    cudaGetSymbolAddress((void**)&p_es0, g_esrc0);
    cudaGetSymbolAddress((void**)&p_ed0, g_edst0);
    cudaGetSymbolAddress((void**)&p_es1, g_esrc1);
    cudaGetSymbolAddress((void**)&p_ed1, g_edst1);
    cudaGetSymbolAddress((void**)&p_cnt, g_cnt);
    cudaGetSymbolAddress((void**)&p_xb,  g_xb);

    k_init<<<(BNUM * 2 * NH + 255) / 256, 256>>>();

    // stage 1: N=100000, F=256, n/graph=2000 -> k=1600
    run_stage(x, FIN, 100000, 2000, 1600, W1, b1, Ws1, bs1,
              ei, ei + E0, p_cnt + 0, p_es0, p_ed0, p_cnt + 1, true);
    // stage 2: N=80000, F=128, n/graph=1600 -> k=1280
    run_stage(p_xb, NH, 80000, 1600, 1280, W2, b2, Ws2, bs2,
              p_es0, p_ed0, p_cnt + 1, p_es1, p_ed1, p_cnt + 2, true);
    // stage 3: N=64000, F=128, n/graph=1280 -> k=1024 (no edge filter needed)
    run_stage(p_xb, NH, 64000, 1280, 1024, W3, b3, Ws3, bs3,
              p_es1, p_ed1, p_cnt + 2, nullptr, nullptr, nullptr, false);

    k_final<<<BNUM, NH>>>(Wl, bl, out);
}